// round 12
// baseline (speedup 1.0000x reference)
#include <cuda_runtime.h>
#include <cuda_bf16.h>
#include <cstdint>

#define N_NODES 50000
#define N_EDGES 800000
#define TWO_N   100000
#define TWO_E   1600000
#define SCAN_BLK 1024
#define SCAN_NBLK ((TWO_N + SCAN_BLK - 1) / SCAN_BLK)   // 98

// ---------------- scratch ----------------------------------------------------
__device__ __align__(16) float g_xw[N_NODES * 256];   // x @ [W0 | W1]
__device__ __align__(16) float g_att[N_NODES * 32];   // [s0(8) d0(8) s1(8) d1(8)]
__device__ __align__(16) __nv_bfloat16 g_Whi[256 * 256];  // [k][n] n: [W0|W1]
__device__ __align__(16) __nv_bfloat16 g_Wlo[256 * 256];
__device__ int   g_deg[TWO_N];     // [0,N): deg0; [N,2N): deg1 (collapsed)
__device__ int   g_off[TWO_N + 1];
__device__ int   g_cur[TWO_N];
__device__ int   g_srcarr[TWO_E];  // hop0: src; hop1: src | (weight<<16)
__device__ int   g_bsum[SCAN_NBLK];
__device__ int   g_bsum_scan[SCAN_NBLK];

__device__ __forceinline__ uint32_t smem_u32(const void* p) {
    uint32_t a;
    asm("{ .reg .u64 t; cvta.to.shared.u64 t, %1; cvt.u32.u64 %0, t; }"
        : "=r"(a) : "l"(p));
    return a;
}

// ---------------- W split kernel ---------------------------------------------
__global__ void wsplit_kernel(const float* __restrict__ W0,
                              const float* __restrict__ W1) {
    int i = blockIdx.x * 256 + threadIdx.x;
    int k = i >> 8, n = i & 255;
    float v = (n < 128) ? W0[k * 128 + n] : W1[k * 128 + (n - 128)];
    __nv_bfloat16 h = __float2bfloat16(v);
    g_Whi[i] = h;
    g_Wlo[i] = __float2bfloat16(v - __bfloat162float(h));
}

// ---------------- HMMA GEMM (split-bf16, 3 terms) + logits epilogue ----------
#define APAD 40
#define BPAD 136

__global__ __launch_bounds__(256) void gemm_hmma_kernel(
        const float* __restrict__ x,
        const float* __restrict__ as0, const float* __restrict__ ad0,
        const float* __restrict__ as1, const float* __restrict__ ad1) {
    __shared__ __nv_bfloat16 sAh[128][APAD];
    __shared__ __nv_bfloat16 sAl[128][APAD];
    __shared__ __nv_bfloat16 sBh[32][BPAD];
    __shared__ __nv_bfloat16 sBl[32][BPAD];

    int tid  = threadIdx.x;
    int wid  = tid >> 5;
    int lane = tid & 31;
    int m0   = blockIdx.x * 128;
    int half = blockIdx.y;
    int m0w  = (wid >> 1) * 32;
    int n0w  = (wid & 1) * 64;

    float acc[2][8][4];
#pragma unroll
    for (int a = 0; a < 2; a++)
#pragma unroll
        for (int b = 0; b < 8; b++)
#pragma unroll
            for (int c = 0; c < 4; c++) acc[a][b][c] = 0.f;

    int arow = tid >> 1, akb = (tid & 1) * 16;
    bool aok = (m0 + arow) < N_NODES;
    int bk = tid >> 3, bnb = (tid & 7) * 16;

    int a_roff = ((lane >> 3) & 1) * 8 + (lane & 7);
    int a_coff = ((lane >> 4) & 1) * 8;
    int b_koff = ((lane >> 3) & 1) * 8 + (lane & 7);
    int b_noff = ((lane >> 4) & 1) * 8;

    for (int kc = 0; kc < 8; kc++) {
        if (kc > 0) __syncthreads();
        {
            const float* src = x + (size_t)(m0 + arow) * 256 + kc * 32 + akb;
#pragma unroll
            for (int i = 0; i < 16; i += 4) {
                float4 v = aok ? *(const float4*)(src + i)
                               : make_float4(0.f, 0.f, 0.f, 0.f);
                float fv[4] = {v.x, v.y, v.z, v.w};
                uint32_t ph[2], pl[2];
#pragma unroll
                for (int j = 0; j < 2; j++) {
                    __nv_bfloat16 h0 = __float2bfloat16(fv[2*j]);
                    __nv_bfloat16 h1 = __float2bfloat16(fv[2*j+1]);
                    __nv_bfloat16 l0 = __float2bfloat16(fv[2*j]   - __bfloat162float(h0));
                    __nv_bfloat16 l1 = __float2bfloat16(fv[2*j+1] - __bfloat162float(h1));
                    ph[j] = (uint32_t)__bfloat16_as_ushort(h0)
                          | ((uint32_t)__bfloat16_as_ushort(h1) << 16);
                    pl[j] = (uint32_t)__bfloat16_as_ushort(l0)
                          | ((uint32_t)__bfloat16_as_ushort(l1) << 16);
                }
                *(uint2*)&sAh[arow][akb + i] = make_uint2(ph[0], ph[1]);
                *(uint2*)&sAl[arow][akb + i] = make_uint2(pl[0], pl[1]);
            }
        }
        {
            const __nv_bfloat16* wh = g_Whi + (size_t)(kc * 32 + bk) * 256 + half * 128 + bnb;
            const __nv_bfloat16* wl = g_Wlo + (size_t)(kc * 32 + bk) * 256 + half * 128 + bnb;
            uint4 vh0 = *(const uint4*)wh;
            uint4 vh1 = *(const uint4*)(wh + 8);
            uint4 vl0 = *(const uint4*)wl;
            uint4 vl1 = *(const uint4*)(wl + 8);
            *(uint4*)&sBh[bk][bnb]     = vh0;
            *(uint4*)&sBh[bk][bnb + 8] = vh1;
            *(uint4*)&sBl[bk][bnb]     = vl0;
            *(uint4*)&sBl[bk][bnb + 8] = vl1;
        }
        __syncthreads();

#pragma unroll
        for (int ks = 0; ks < 2; ks++) {
            int k0 = ks * 16;
            uint32_t ah[2][4], al[2][4], bb[4][4];
#pragma unroll
            for (int mt = 0; mt < 2; mt++) {
                uint32_t adrh = smem_u32(&sAh[m0w + mt * 16 + a_roff][k0 + a_coff]);
                asm volatile("ldmatrix.sync.aligned.m8n8.x4.shared.b16 {%0,%1,%2,%3}, [%4];"
                    : "=r"(ah[mt][0]), "=r"(ah[mt][1]), "=r"(ah[mt][2]), "=r"(ah[mt][3])
                    : "r"(adrh));
                uint32_t adrl = smem_u32(&sAl[m0w + mt * 16 + a_roff][k0 + a_coff]);
                asm volatile("ldmatrix.sync.aligned.m8n8.x4.shared.b16 {%0,%1,%2,%3}, [%4];"
                    : "=r"(al[mt][0]), "=r"(al[mt][1]), "=r"(al[mt][2]), "=r"(al[mt][3])
                    : "r"(adrl));
            }
#pragma unroll
            for (int p = 0; p < 4; p++) {
                uint32_t adr = smem_u32(&sBh[k0 + b_koff][n0w + p * 16 + b_noff]);
                asm volatile("ldmatrix.sync.aligned.m8n8.x4.trans.shared.b16 {%0,%1,%2,%3}, [%4];"
                    : "=r"(bb[p][0]), "=r"(bb[p][1]), "=r"(bb[p][2]), "=r"(bb[p][3])
                    : "r"(adr));
            }
#pragma unroll
            for (int mt = 0; mt < 2; mt++)
#pragma unroll
                for (int nt = 0; nt < 8; nt++) {
                    uint32_t b0 = bb[nt >> 1][(nt & 1) * 2];
                    uint32_t b1 = bb[nt >> 1][(nt & 1) * 2 + 1];
                    float* d = acc[mt][nt];
                    asm volatile(
                        "mma.sync.aligned.m16n8k16.row.col.f32.bf16.bf16.f32 "
                        "{%0,%1,%2,%3}, {%4,%5,%6,%7}, {%8,%9}, {%0,%1,%2,%3};"
                        : "+f"(d[0]), "+f"(d[1]), "+f"(d[2]), "+f"(d[3])
                        : "r"(ah[mt][0]), "r"(ah[mt][1]), "r"(ah[mt][2]), "r"(ah[mt][3]),
                          "r"(b0), "r"(b1));
                    asm volatile(
                        "mma.sync.aligned.m16n8k16.row.col.f32.bf16.bf16.f32 "
                        "{%0,%1,%2,%3}, {%4,%5,%6,%7}, {%8,%9}, {%0,%1,%2,%3};"
                        : "+f"(d[0]), "+f"(d[1]), "+f"(d[2]), "+f"(d[3])
                        : "r"(al[mt][0]), "r"(al[mt][1]), "r"(al[mt][2]), "r"(al[mt][3]),
                          "r"(b0), "r"(b1));
                }
#pragma unroll
            for (int p = 0; p < 4; p++) {
                uint32_t adr = smem_u32(&sBl[k0 + b_koff][n0w + p * 16 + b_noff]);
                asm volatile("ldmatrix.sync.aligned.m8n8.x4.trans.shared.b16 {%0,%1,%2,%3}, [%4];"
                    : "=r"(bb[p][0]), "=r"(bb[p][1]), "=r"(bb[p][2]), "=r"(bb[p][3])
                    : "r"(adr));
            }
#pragma unroll
            for (int mt = 0; mt < 2; mt++)
#pragma unroll
                for (int nt = 0; nt < 8; nt++) {
                    uint32_t b0 = bb[nt >> 1][(nt & 1) * 2];
                    uint32_t b1 = bb[nt >> 1][(nt & 1) * 2 + 1];
                    float* d = acc[mt][nt];
                    asm volatile(
                        "mma.sync.aligned.m16n8k16.row.col.f32.bf16.bf16.f32 "
                        "{%0,%1,%2,%3}, {%4,%5,%6,%7}, {%8,%9}, {%0,%1,%2,%3};"
                        : "+f"(d[0]), "+f"(d[1]), "+f"(d[2]), "+f"(d[3])
                        : "r"(ah[mt][0]), "r"(ah[mt][1]), "r"(ah[mt][2]), "r"(ah[mt][3]),
                          "r"(b0), "r"(b1));
                }
        }
    }

    // ---- epilogue: store xw + attention logits ----
#pragma unroll
    for (int mt = 0; mt < 2; mt++) {
        int r0 = m0 + m0w + mt * 16 + (lane >> 2);
        int r1 = r0 + 8;
        bool ok0 = r0 < N_NODES, ok1 = r1 < N_NODES;
#pragma unroll
        for (int nt = 0; nt < 8; nt++) {
            int col = half * 128 + n0w + nt * 8 + (lane & 3) * 2;
            if (ok0) *(float2*)&g_xw[(size_t)r0 * 256 + col] =
                make_float2(acc[mt][nt][0], acc[mt][nt][1]);
            if (ok1) *(float2*)&g_xw[(size_t)r1 * 256 + col] =
                make_float2(acc[mt][nt][2], acc[mt][nt][3]);
        }
    }

    const float* asv = half ? as1 : as0;
    const float* adv = half ? ad1 : ad0;
    float asr[16], adr_[16];
#pragma unroll
    for (int nt = 0; nt < 8; nt++) {
        int c = n0w + nt * 8 + (lane & 3) * 2;
        asr[nt * 2]     = asv[c];
        asr[nt * 2 + 1] = asv[c + 1];
        adr_[nt * 2]     = adv[c];
        adr_[nt * 2 + 1] = adv[c + 1];
    }
#pragma unroll
    for (int mt = 0; mt < 2; mt++) {
#pragma unroll
        for (int rh = 0; rh < 2; rh++) {
            float ps[4] = {0.f, 0.f, 0.f, 0.f};
            float pd[4] = {0.f, 0.f, 0.f, 0.f};
#pragma unroll
            for (int nt = 0; nt < 8; nt++) {
                int h = nt >> 1;
                float a0 = acc[mt][nt][rh * 2];
                float a1 = acc[mt][nt][rh * 2 + 1];
                ps[h] += a0 * asr[nt * 2] + a1 * asr[nt * 2 + 1];
                pd[h] += a0 * adr_[nt * 2] + a1 * adr_[nt * 2 + 1];
            }
#pragma unroll
            for (int off = 1; off < 4; off <<= 1) {
#pragma unroll
                for (int h = 0; h < 4; h++) {
                    ps[h] += __shfl_xor_sync(0xffffffffu, ps[h], off);
                    pd[h] += __shfl_xor_sync(0xffffffffu, pd[h], off);
                }
            }
            int r = m0 + m0w + mt * 16 + rh * 8 + (lane >> 2);
            if ((lane & 3) == 0 && r < N_NODES) {
#pragma unroll
                for (int h = 0; h < 4; h++) {
                    int gh = (n0w >> 4) + h;
                    g_att[r * 32 + half * 16 + gh]     = ps[h];
                    g_att[r * 32 + half * 16 + 8 + gh] = pd[h];
                }
            }
        }
    }
}

// ---------------- zero degree counters ---------------------------------------
__global__ void zero_kernel() {
    int i = blockIdx.x * blockDim.x + threadIdx.x;
    if (i < TWO_N) g_deg[i] = 0;
}

// ---------------- count0: hop-0 in-degrees -----------------------------------
__global__ void count0_kernel(const int* __restrict__ col) {
    int e = blockIdx.x * blockDim.x + threadIdx.x;
    if (e >= N_EDGES) return;
    atomicAdd(&g_deg[col[e]], 1);
}

// ---------------- count1: collapsed hop-1 degrees ----------------------------
__global__ void count1_kernel(const int* __restrict__ col) {
    int c = blockIdx.x * blockDim.x + threadIdx.x;
    if (c >= N_NODES) return;
    if (g_deg[c] > 0) atomicAdd(&g_deg[N_NODES + col[c]], 1);
}

// ---------------- exclusive scan (3 stages) ----------------------------------
__global__ void scanA_kernel() {
    __shared__ int sh[SCAN_BLK];
    int t = threadIdx.x;
    int i = blockIdx.x * SCAN_BLK + t;
    int v = (i < TWO_N) ? g_deg[i] : 0;
    sh[t] = v;
    __syncthreads();
    for (int off = 1; off < SCAN_BLK; off <<= 1) {
        int add = (t >= off) ? sh[t - off] : 0;
        __syncthreads();
        sh[t] += add;
        __syncthreads();
    }
    if (i < TWO_N) g_off[i] = sh[t] - v;
    if (t == SCAN_BLK - 1) g_bsum[blockIdx.x] = sh[SCAN_BLK - 1];
}

__global__ void scanB_kernel() {
    __shared__ int sh[128];
    int t = threadIdx.x;
    int v = (t < SCAN_NBLK) ? g_bsum[t] : 0;
    sh[t] = v;
    __syncthreads();
    for (int off = 1; off < 128; off <<= 1) {
        int add = (t >= off) ? sh[t - off] : 0;
        __syncthreads();
        sh[t] += add;
        __syncthreads();
    }
    if (t < SCAN_NBLK) g_bsum_scan[t] = sh[t] - v;
}

__global__ void scanC_kernel() {
    int i = blockIdx.x * SCAN_BLK + threadIdx.x;
    if (i < TWO_N) {
        int v = g_off[i] + g_bsum_scan[blockIdx.x];
        g_off[i] = v;
        g_cur[i] = v;
        if (i == TWO_N - 1) g_off[TWO_N] = v + g_deg[i];
    }
}

// ---------------- scatter0: hop-0 edges --------------------------------------
__global__ void scatter0_kernel(const int* __restrict__ row,
                                const int* __restrict__ col) {
    int e = blockIdx.x * blockDim.x + threadIdx.x;
    if (e >= N_EDGES) return;
    int p = atomicAdd(&g_cur[col[e]], 1);
    g_srcarr[p] = row[e];
}

// ---------------- scatter1: collapsed hop-1 entries (src | weight<<16) -------
__global__ void scatter1_kernel(const int* __restrict__ row,
                                const int* __restrict__ col) {
    int c = blockIdx.x * blockDim.x + threadIdx.x;
    if (c >= N_NODES) return;
    int w = g_deg[c];
    if (w <= 0) return;
    int p = atomicAdd(&g_cur[N_NODES + col[c]], 1);
    g_srcarr[p] = row[c] | (w << 16);
}

// ---------------- fused aggregation + residual + LayerNorm -------------------
__global__ void agg_ln_kernel(const float* __restrict__ b0,
                              const float* __restrict__ b1,
                              const float* __restrict__ x,
                              const float* __restrict__ gamma,
                              const float* __restrict__ beta,
                              float* __restrict__ out) {
    int n = (blockIdx.x * blockDim.x + threadIdx.x) >> 5;
    if (n >= N_NODES) return;
    int lane = threadIdx.x & 31;
    int head = lane >> 2;
    int c0 = lane * 4;

    // ---- hop 0 ----
    float ad = g_att[n * 32 + 8 + head];
    float t  = g_att[n * 32 + head] + ad;
    t = (t > 0.f) ? t : 0.2f * t;
    float p = __expf(t);
    float sum0 = p;
    float4 v = *(const float4*)&g_xw[n * 256 + c0];
    float4 acc0 = make_float4(p * v.x, p * v.y, p * v.z, p * v.w);
    int je = g_off[n + 1];
    for (int j = g_off[n]; j < je; j++) {
        int src = g_srcarr[j];
        float tt = g_att[src * 32 + head] + ad;
        tt = (tt > 0.f) ? tt : 0.2f * tt;
        float pp = __expf(tt);
        sum0 += pp;
        float4 w = *(const float4*)&g_xw[src * 256 + c0];
        acc0.x += pp * w.x; acc0.y += pp * w.y;
        acc0.z += pp * w.z; acc0.w += pp * w.w;
    }

    // ---- hop 1 (collapsed weighted entries; self doubled) ----
    ad = g_att[n * 32 + 24 + head];
    t  = g_att[n * 32 + 16 + head] + ad;
    t = (t > 0.f) ? t : 0.2f * t;
    p = 2.0f * __expf(t);
    float sum1 = p;
    v = *(const float4*)&g_xw[n * 256 + 128 + c0];
    float4 acc1 = make_float4(p * v.x, p * v.y, p * v.z, p * v.w);
    je = g_off[N_NODES + n + 1];
    for (int j = g_off[N_NODES + n]; j < je; j++) {
        int ent = g_srcarr[j];
        int src = ent & 0xFFFF;
        float wgt = (float)(ent >> 16);
        float tt = g_att[src * 32 + 16 + head] + ad;
        tt = (tt > 0.f) ? tt : 0.2f * tt;
        float pp = wgt * __expf(tt);
        sum1 += pp;
        float4 w = *(const float4*)&g_xw[src * 256 + 128 + c0];
        acc1.x += pp * w.x; acc1.y += pp * w.y;
        acc1.z += pp * w.z; acc1.w += pp * w.w;
    }

    // ---- bias + residual + LN ----
    float i0 = 1.f / sum0, i1 = 1.f / sum1;
    float4 bb0 = *(const float4*)&b0[c0];
    float4 bb1 = *(const float4*)&b1[c0];
    float4 x0 = *(const float4*)&x[n * 256 + c0];
    float4 x1 = *(const float4*)&x[n * 256 + 128 + c0];
    float vv[8];
    vv[0] = acc0.x * i0 + bb0.x + x0.x;
    vv[1] = acc0.y * i0 + bb0.y + x0.y;
    vv[2] = acc0.z * i0 + bb0.z + x0.z;
    vv[3] = acc0.w * i0 + bb0.w + x0.w;
    vv[4] = acc1.x * i1 + bb1.x + x1.x;
    vv[5] = acc1.y * i1 + bb1.y + x1.y;
    vv[6] = acc1.z * i1 + bb1.z + x1.z;
    vv[7] = acc1.w * i1 + bb1.w + x1.w;

    float s = 0.f, s2 = 0.f;
#pragma unroll
    for (int i = 0; i < 8; i++) { s += vv[i]; s2 += vv[i] * vv[i]; }
#pragma unroll
    for (int off = 16; off > 0; off >>= 1) {
        s  += __shfl_xor_sync(0xffffffffu, s, off);
        s2 += __shfl_xor_sync(0xffffffffu, s2, off);
    }
    float mean = s * (1.f / 256.f);
    float var  = s2 * (1.f / 256.f) - mean * mean;
    float rs   = rsqrtf(var + 1e-5f);

    float4 g0 = *(const float4*)&gamma[c0];
    float4 g1 = *(const float4*)&gamma[128 + c0];
    float4 be0 = *(const float4*)&beta[c0];
    float4 be1 = *(const float4*)&beta[128 + c0];
    float4 o0, o1;
    o0.x = (vv[0] - mean) * rs * g0.x + be0.x;
    o0.y = (vv[1] - mean) * rs * g0.y + be0.y;
    o0.z = (vv[2] - mean) * rs * g0.z + be0.z;
    o0.w = (vv[3] - mean) * rs * g0.w + be0.w;
    o1.x = (vv[4] - mean) * rs * g1.x + be1.x;
    o1.y = (vv[5] - mean) * rs * g1.y + be1.y;
    o1.z = (vv[6] - mean) * rs * g1.z + be1.z;
    o1.w = (vv[7] - mean) * rs * g1.w + be1.w;
    *(float4*)&out[n * 256 + c0]       = o0;
    *(float4*)&out[n * 256 + 128 + c0] = o1;
}

// ---------------- launch: fork CSR chain || GEMM chain, join before agg ------
extern "C" void kernel_launch(void* const* d_in, const int* in_sizes, int n_in,
                              void* d_out, int out_size) {
    const float* x     = (const float*)d_in[0];
    const int*   ei    = (const int*)d_in[1];
    const float* W0    = (const float*)d_in[2];
    const float* as0   = (const float*)d_in[3];
    const float* ad0   = (const float*)d_in[4];
    const float* b0    = (const float*)d_in[5];
    const float* W1    = (const float*)d_in[6];
    const float* as1   = (const float*)d_in[7];
    const float* ad1   = (const float*)d_in[8];
    const float* b1    = (const float*)d_in[9];
    const float* gamma = (const float*)d_in[10];
    const float* beta  = (const float*)d_in[11];
    float* out = (float*)d_out;

    const int* row = ei;
    const int* col = ei + N_EDGES;

    static cudaStream_t s2 = nullptr;
    static cudaEvent_t evA = nullptr, evB = nullptr;
    if (s2 == nullptr) {
        cudaStreamCreateWithFlags(&s2, cudaStreamNonBlocking);
        cudaEventCreateWithFlags(&evA, cudaEventDisableTiming);
        cudaEventCreateWithFlags(&evB, cudaEventDisableTiming);
    }

    // fork: CSR chain on s2
    cudaEventRecord(evA, 0);
    cudaStreamWaitEvent(s2, evA, 0);

    zero_kernel<<<(TWO_N + 255) / 256, 256, 0, s2>>>();
    count0_kernel<<<(N_EDGES + 255) / 256, 256, 0, s2>>>(col);
    count1_kernel<<<(N_NODES + 255) / 256, 256, 0, s2>>>(col);
    scanA_kernel<<<SCAN_NBLK, SCAN_BLK, 0, s2>>>();
    scanB_kernel<<<1, 128, 0, s2>>>();
    scanC_kernel<<<SCAN_NBLK, SCAN_BLK, 0, s2>>>();
    scatter0_kernel<<<(N_EDGES + 255) / 256, 256, 0, s2>>>(row, col);
    scatter1_kernel<<<(N_NODES + 255) / 256, 256, 0, s2>>>(row, col);

    // GEMM chain on capture stream
    wsplit_kernel<<<256, 256>>>(W0, W1);
    gemm_hmma_kernel<<<dim3((N_NODES + 127) / 128, 2), 256>>>(x, as0, ad0, as1, ad1);

    // join
    cudaEventRecord(evB, s2);
    cudaStreamWaitEvent(0, evB, 0);

    agg_ln_kernel<<<(N_NODES * 32 + 255) / 256, 256>>>(b0, b1, x, gamma, beta, out);
}

// round 13
// speedup vs baseline: 1.1073x; 1.1073x over previous
#include <cuda_runtime.h>
#include <cuda_bf16.h>
#include <cstdint>

#define N_NODES 50000
#define N_EDGES 800000
#define TWO_N   100000
#define TWO_E   1600000
#define SCAN_BLK 1024
#define SCAN_NBLK ((TWO_N + SCAN_BLK - 1) / SCAN_BLK)   // 98

// ---------------- scratch ----------------------------------------------------
__device__ __align__(16) float g_xw[N_NODES * 256];   // x @ [W0 | W1]
__device__ __align__(16) float g_att[N_NODES * 32];   // [s0(8) d0(8) s1(8) d1(8)]
__device__ __align__(16) __nv_bfloat16 g_Whi[256 * 256];  // [k][n] n: [W0|W1]
__device__ __align__(16) __nv_bfloat16 g_Wlo[256 * 256];
__device__ int   g_deg[TWO_N];     // [0,N): deg0; [N,2N): deg1 (collapsed)
__device__ int   g_off[TWO_N + 1];
__device__ int   g_cur[TWO_N];
__device__ int   g_srcarr[TWO_E];  // hop0: src; hop1: src | (weight<<16)
__device__ int   g_bsum[SCAN_NBLK];
__device__ int   g_bsum_scan[SCAN_NBLK];

__device__ __forceinline__ uint32_t smem_u32(const void* p) {
    uint32_t a;
    asm("{ .reg .u64 t; cvta.to.shared.u64 t, %1; cvt.u32.u64 %0, t; }"
        : "=r"(a) : "l"(p));
    return a;
}

// ---------------- W split kernel ---------------------------------------------
__global__ void wsplit_kernel(const float* __restrict__ W0,
                              const float* __restrict__ W1) {
    int i = blockIdx.x * 256 + threadIdx.x;
    int k = i >> 8, n = i & 255;
    float v = (n < 128) ? W0[k * 128 + n] : W1[k * 128 + (n - 128)];
    __nv_bfloat16 h = __float2bfloat16(v);
    g_Whi[i] = h;
    g_Wlo[i] = __float2bfloat16(v - __bfloat162float(h));
}

// ---------------- HMMA GEMM (split-bf16, 3 terms), double-buffered -----------
#define APAD 40
#define BPAD 136
// element offsets within one stage (in bf16 elements)
#define OA_H 0
#define OA_L 5120                 // 128*40
#define OB_H 10240                // + 128*40
#define OB_L 14592                // + 32*136
#define STAGE_ELEMS 18944         // 10240 + 8704 = per-stage total
#define GEMM_SMEM_BYTES (2 * STAGE_ELEMS * 2)   // 75,776 B

__global__ __launch_bounds__(256) void gemm_hmma_kernel(
        const float* __restrict__ x,
        const float* __restrict__ as0, const float* __restrict__ ad0,
        const float* __restrict__ as1, const float* __restrict__ ad1) {
    extern __shared__ __nv_bfloat16 smem[];

    int tid  = threadIdx.x;
    int wid  = tid >> 5;
    int lane = tid & 31;
    int m0   = blockIdx.x * 128;
    int half = blockIdx.y;
    int m0w  = (wid >> 1) * 32;
    int n0w  = (wid & 1) * 64;

    float acc[2][8][4];
#pragma unroll
    for (int a = 0; a < 2; a++)
#pragma unroll
        for (int b = 0; b < 8; b++)
#pragma unroll
            for (int c = 0; c < 4; c++) acc[a][b][c] = 0.f;

    int arow = tid >> 1, akb = (tid & 1) * 16;
    bool aok = (m0 + arow) < N_NODES;
    int bk = tid >> 3, bnb = (tid & 7) * 16;

    int a_roff = ((lane >> 3) & 1) * 8 + (lane & 7);
    int a_coff = ((lane >> 4) & 1) * 8;
    int b_koff = ((lane >> 3) & 1) * 8 + (lane & 7);
    int b_noff = ((lane >> 4) & 1) * 8;

    // staged registers for one K-chunk
    float4 areg[4];
    uint4  bregh[2], bregl[2];

    // preload chunk 0
    {
        const float* src = x + (size_t)(m0 + arow) * 256 + akb;
#pragma unroll
        for (int i = 0; i < 4; i++)
            areg[i] = aok ? *(const float4*)(src + i * 4)
                          : make_float4(0.f, 0.f, 0.f, 0.f);
        const __nv_bfloat16* wh = g_Whi + (size_t)bk * 256 + half * 128 + bnb;
        const __nv_bfloat16* wl = g_Wlo + (size_t)bk * 256 + half * 128 + bnb;
        bregh[0] = *(const uint4*)wh;
        bregh[1] = *(const uint4*)(wh + 8);
        bregl[0] = *(const uint4*)wl;
        bregl[1] = *(const uint4*)(wl + 8);
    }

    int buf = 0;
    for (int kc = 0; kc < 8; kc++) {
        __nv_bfloat16* st = smem + buf * STAGE_ELEMS;

        // ---- store staged regs -> smem (A converted to hi/lo bf16) ----
#pragma unroll
        for (int i = 0; i < 4; i++) {
            float fv[4] = {areg[i].x, areg[i].y, areg[i].z, areg[i].w};
            uint32_t ph[2], pl[2];
#pragma unroll
            for (int j = 0; j < 2; j++) {
                __nv_bfloat16 h0 = __float2bfloat16(fv[2*j]);
                __nv_bfloat16 h1 = __float2bfloat16(fv[2*j+1]);
                __nv_bfloat16 l0 = __float2bfloat16(fv[2*j]   - __bfloat162float(h0));
                __nv_bfloat16 l1 = __float2bfloat16(fv[2*j+1] - __bfloat162float(h1));
                ph[j] = (uint32_t)__bfloat16_as_ushort(h0)
                      | ((uint32_t)__bfloat16_as_ushort(h1) << 16);
                pl[j] = (uint32_t)__bfloat16_as_ushort(l0)
                      | ((uint32_t)__bfloat16_as_ushort(l1) << 16);
            }
            *(uint2*)&st[OA_H + arow * APAD + akb + i * 4] = make_uint2(ph[0], ph[1]);
            *(uint2*)&st[OA_L + arow * APAD + akb + i * 4] = make_uint2(pl[0], pl[1]);
        }
        *(uint4*)&st[OB_H + bk * BPAD + bnb]     = bregh[0];
        *(uint4*)&st[OB_H + bk * BPAD + bnb + 8] = bregh[1];
        *(uint4*)&st[OB_L + bk * BPAD + bnb]     = bregl[0];
        *(uint4*)&st[OB_L + bk * BPAD + bnb + 8] = bregl[1];
        __syncthreads();

        // ---- prefetch chunk kc+1 (overlaps MMA below) ----
        if (kc < 7) {
            int kn = (kc + 1) * 32;
            const float* src = x + (size_t)(m0 + arow) * 256 + kn + akb;
#pragma unroll
            for (int i = 0; i < 4; i++)
                areg[i] = aok ? *(const float4*)(src + i * 4)
                              : make_float4(0.f, 0.f, 0.f, 0.f);
            const __nv_bfloat16* wh = g_Whi + (size_t)(kn + bk) * 256 + half * 128 + bnb;
            const __nv_bfloat16* wl = g_Wlo + (size_t)(kn + bk) * 256 + half * 128 + bnb;
            bregh[0] = *(const uint4*)wh;
            bregh[1] = *(const uint4*)(wh + 8);
            bregl[0] = *(const uint4*)wl;
            bregl[1] = *(const uint4*)(wl + 8);
        }

        // ---- MMA over this stage ----
#pragma unroll
        for (int ks = 0; ks < 2; ks++) {
            int k0 = ks * 16;
            uint32_t ah[2][4], al[2][4], bb[4][4];
#pragma unroll
            for (int mt = 0; mt < 2; mt++) {
                uint32_t adrh = smem_u32(&st[OA_H + (m0w + mt * 16 + a_roff) * APAD + k0 + a_coff]);
                asm volatile("ldmatrix.sync.aligned.m8n8.x4.shared.b16 {%0,%1,%2,%3}, [%4];"
                    : "=r"(ah[mt][0]), "=r"(ah[mt][1]), "=r"(ah[mt][2]), "=r"(ah[mt][3])
                    : "r"(adrh));
                uint32_t adrl = smem_u32(&st[OA_L + (m0w + mt * 16 + a_roff) * APAD + k0 + a_coff]);
                asm volatile("ldmatrix.sync.aligned.m8n8.x4.shared.b16 {%0,%1,%2,%3}, [%4];"
                    : "=r"(al[mt][0]), "=r"(al[mt][1]), "=r"(al[mt][2]), "=r"(al[mt][3])
                    : "r"(adrl));
            }
#pragma unroll
            for (int p = 0; p < 4; p++) {
                uint32_t adr = smem_u32(&st[OB_H + (k0 + b_koff) * BPAD + n0w + p * 16 + b_noff]);
                asm volatile("ldmatrix.sync.aligned.m8n8.x4.trans.shared.b16 {%0,%1,%2,%3}, [%4];"
                    : "=r"(bb[p][0]), "=r"(bb[p][1]), "=r"(bb[p][2]), "=r"(bb[p][3])
                    : "r"(adr));
            }
#pragma unroll
            for (int mt = 0; mt < 2; mt++)
#pragma unroll
                for (int nt = 0; nt < 8; nt++) {
                    uint32_t b0 = bb[nt >> 1][(nt & 1) * 2];
                    uint32_t b1 = bb[nt >> 1][(nt & 1) * 2 + 1];
                    float* d = acc[mt][nt];
                    asm volatile(
                        "mma.sync.aligned.m16n8k16.row.col.f32.bf16.bf16.f32 "
                        "{%0,%1,%2,%3}, {%4,%5,%6,%7}, {%8,%9}, {%0,%1,%2,%3};"
                        : "+f"(d[0]), "+f"(d[1]), "+f"(d[2]), "+f"(d[3])
                        : "r"(ah[mt][0]), "r"(ah[mt][1]), "r"(ah[mt][2]), "r"(ah[mt][3]),
                          "r"(b0), "r"(b1));
                    asm volatile(
                        "mma.sync.aligned.m16n8k16.row.col.f32.bf16.bf16.f32 "
                        "{%0,%1,%2,%3}, {%4,%5,%6,%7}, {%8,%9}, {%0,%1,%2,%3};"
                        : "+f"(d[0]), "+f"(d[1]), "+f"(d[2]), "+f"(d[3])
                        : "r"(al[mt][0]), "r"(al[mt][1]), "r"(al[mt][2]), "r"(al[mt][3]),
                          "r"(b0), "r"(b1));
                }
#pragma unroll
            for (int p = 0; p < 4; p++) {
                uint32_t adr = smem_u32(&st[OB_L + (k0 + b_koff) * BPAD + n0w + p * 16 + b_noff]);
                asm volatile("ldmatrix.sync.aligned.m8n8.x4.trans.shared.b16 {%0,%1,%2,%3}, [%4];"
                    : "=r"(bb[p][0]), "=r"(bb[p][1]), "=r"(bb[p][2]), "=r"(bb[p][3])
                    : "r"(adr));
            }
#pragma unroll
            for (int mt = 0; mt < 2; mt++)
#pragma unroll
                for (int nt = 0; nt < 8; nt++) {
                    uint32_t b0 = bb[nt >> 1][(nt & 1) * 2];
                    uint32_t b1 = bb[nt >> 1][(nt & 1) * 2 + 1];
                    float* d = acc[mt][nt];
                    asm volatile(
                        "mma.sync.aligned.m16n8k16.row.col.f32.bf16.bf16.f32 "
                        "{%0,%1,%2,%3}, {%4,%5,%6,%7}, {%8,%9}, {%0,%1,%2,%3};"
                        : "+f"(d[0]), "+f"(d[1]), "+f"(d[2]), "+f"(d[3])
                        : "r"(ah[mt][0]), "r"(ah[mt][1]), "r"(ah[mt][2]), "r"(ah[mt][3]),
                          "r"(b0), "r"(b1));
                }
        }
        buf ^= 1;
    }

    // ---- epilogue: store xw + attention logits ----
#pragma unroll
    for (int mt = 0; mt < 2; mt++) {
        int r0 = m0 + m0w + mt * 16 + (lane >> 2);
        int r1 = r0 + 8;
        bool ok0 = r0 < N_NODES, ok1 = r1 < N_NODES;
#pragma unroll
        for (int nt = 0; nt < 8; nt++) {
            int col = half * 128 + n0w + nt * 8 + (lane & 3) * 2;
            if (ok0) *(float2*)&g_xw[(size_t)r0 * 256 + col] =
                make_float2(acc[mt][nt][0], acc[mt][nt][1]);
            if (ok1) *(float2*)&g_xw[(size_t)r1 * 256 + col] =
                make_float2(acc[mt][nt][2], acc[mt][nt][3]);
        }
    }

    const float* asv = half ? as1 : as0;
    const float* adv = half ? ad1 : ad0;
    float asr[16], adr_[16];
#pragma unroll
    for (int nt = 0; nt < 8; nt++) {
        int c = n0w + nt * 8 + (lane & 3) * 2;
        asr[nt * 2]     = asv[c];
        asr[nt * 2 + 1] = asv[c + 1];
        adr_[nt * 2]     = adv[c];
        adr_[nt * 2 + 1] = adv[c + 1];
    }
#pragma unroll
    for (int mt = 0; mt < 2; mt++) {
#pragma unroll
        for (int rh = 0; rh < 2; rh++) {
            float ps[4] = {0.f, 0.f, 0.f, 0.f};
            float pd[4] = {0.f, 0.f, 0.f, 0.f};
#pragma unroll
            for (int nt = 0; nt < 8; nt++) {
                int h = nt >> 1;
                float a0 = acc[mt][nt][rh * 2];
                float a1 = acc[mt][nt][rh * 2 + 1];
                ps[h] += a0 * asr[nt * 2] + a1 * asr[nt * 2 + 1];
                pd[h] += a0 * adr_[nt * 2] + a1 * adr_[nt * 2 + 1];
            }
#pragma unroll
            for (int off = 1; off < 4; off <<= 1) {
#pragma unroll
                for (int h = 0; h < 4; h++) {
                    ps[h] += __shfl_xor_sync(0xffffffffu, ps[h], off);
                    pd[h] += __shfl_xor_sync(0xffffffffu, pd[h], off);
                }
            }
            int r = m0 + m0w + mt * 16 + rh * 8 + (lane >> 2);
            if ((lane & 3) == 0 && r < N_NODES) {
#pragma unroll
                for (int h = 0; h < 4; h++) {
                    int gh = (n0w >> 4) + h;
                    g_att[r * 32 + half * 16 + gh]     = ps[h];
                    g_att[r * 32 + half * 16 + 8 + gh] = pd[h];
                }
            }
        }
    }
}

// ---------------- zero degree counters ---------------------------------------
__global__ void zero_kernel() {
    int i = blockIdx.x * blockDim.x + threadIdx.x;
    if (i < TWO_N) g_deg[i] = 0;
}

// ---------------- count0: hop-0 in-degrees -----------------------------------
__global__ void count0_kernel(const int* __restrict__ col) {
    int e = blockIdx.x * blockDim.x + threadIdx.x;
    if (e >= N_EDGES) return;
    atomicAdd(&g_deg[col[e]], 1);
}

// ---------------- count1: collapsed hop-1 degrees ----------------------------
__global__ void count1_kernel(const int* __restrict__ col) {
    int c = blockIdx.x * blockDim.x + threadIdx.x;
    if (c >= N_NODES) return;
    if (g_deg[c] > 0) atomicAdd(&g_deg[N_NODES + col[c]], 1);
}

// ---------------- exclusive scan (3 stages) ----------------------------------
__global__ void scanA_kernel() {
    __shared__ int sh[SCAN_BLK];
    int t = threadIdx.x;
    int i = blockIdx.x * SCAN_BLK + t;
    int v = (i < TWO_N) ? g_deg[i] : 0;
    sh[t] = v;
    __syncthreads();
    for (int off = 1; off < SCAN_BLK; off <<= 1) {
        int add = (t >= off) ? sh[t - off] : 0;
        __syncthreads();
        sh[t] += add;
        __syncthreads();
    }
    if (i < TWO_N) g_off[i] = sh[t] - v;
    if (t == SCAN_BLK - 1) g_bsum[blockIdx.x] = sh[SCAN_BLK - 1];
}

__global__ void scanB_kernel() {
    __shared__ int sh[128];
    int t = threadIdx.x;
    int v = (t < SCAN_NBLK) ? g_bsum[t] : 0;
    sh[t] = v;
    __syncthreads();
    for (int off = 1; off < 128; off <<= 1) {
        int add = (t >= off) ? sh[t - off] : 0;
        __syncthreads();
        sh[t] += add;
        __syncthreads();
    }
    if (t < SCAN_NBLK) g_bsum_scan[t] = sh[t] - v;
}

__global__ void scanC_kernel() {
    int i = blockIdx.x * SCAN_BLK + threadIdx.x;
    if (i < TWO_N) {
        int v = g_off[i] + g_bsum_scan[blockIdx.x];
        g_off[i] = v;
        g_cur[i] = v;
        if (i == TWO_N - 1) g_off[TWO_N] = v + g_deg[i];
    }
}

// ---------------- scatter0: hop-0 edges --------------------------------------
__global__ void scatter0_kernel(const int* __restrict__ row,
                                const int* __restrict__ col) {
    int e = blockIdx.x * blockDim.x + threadIdx.x;
    if (e >= N_EDGES) return;
    int p = atomicAdd(&g_cur[col[e]], 1);
    g_srcarr[p] = row[e];
}

// ---------------- scatter1: collapsed hop-1 entries (src | weight<<16) -------
__global__ void scatter1_kernel(const int* __restrict__ row,
                                const int* __restrict__ col) {
    int c = blockIdx.x * blockDim.x + threadIdx.x;
    if (c >= N_NODES) return;
    int w = g_deg[c];
    if (w <= 0) return;
    int p = atomicAdd(&g_cur[N_NODES + col[c]], 1);
    g_srcarr[p] = row[c] | (w << 16);
}

// ---------------- fused aggregation + residual + LayerNorm -------------------
__global__ void agg_ln_kernel(const float* __restrict__ b0,
                              const float* __restrict__ b1,
                              const float* __restrict__ x,
                              const float* __restrict__ gamma,
                              const float* __restrict__ beta,
                              float* __restrict__ out) {
    int n = (blockIdx.x * blockDim.x + threadIdx.x) >> 5;
    if (n >= N_NODES) return;
    int lane = threadIdx.x & 31;
    int head = lane >> 2;
    int c0 = lane * 4;

    // ---- hop 0 ----
    float ad = g_att[n * 32 + 8 + head];
    float t  = g_att[n * 32 + head] + ad;
    t = (t > 0.f) ? t : 0.2f * t;
    float p = __expf(t);
    float sum0 = p;
    float4 v = *(const float4*)&g_xw[n * 256 + c0];
    float4 acc0 = make_float4(p * v.x, p * v.y, p * v.z, p * v.w);
    int je = g_off[n + 1];
    for (int j = g_off[n]; j < je; j++) {
        int src = g_srcarr[j];
        float tt = g_att[src * 32 + head] + ad;
        tt = (tt > 0.f) ? tt : 0.2f * tt;
        float pp = __expf(tt);
        sum0 += pp;
        float4 w = *(const float4*)&g_xw[src * 256 + c0];
        acc0.x += pp * w.x; acc0.y += pp * w.y;
        acc0.z += pp * w.z; acc0.w += pp * w.w;
    }

    // ---- hop 1 (collapsed weighted entries; self doubled) ----
    ad = g_att[n * 32 + 24 + head];
    t  = g_att[n * 32 + 16 + head] + ad;
    t = (t > 0.f) ? t : 0.2f * t;
    p = 2.0f * __expf(t);
    float sum1 = p;
    v = *(const float4*)&g_xw[n * 256 + 128 + c0];
    float4 acc1 = make_float4(p * v.x, p * v.y, p * v.z, p * v.w);
    je = g_off[N_NODES + n + 1];
    for (int j = g_off[N_NODES + n]; j < je; j++) {
        int ent = g_srcarr[j];
        int src = ent & 0xFFFF;
        float wgt = (float)(ent >> 16);
        float tt = g_att[src * 32 + 16 + head] + ad;
        tt = (tt > 0.f) ? tt : 0.2f * tt;
        float pp = wgt * __expf(tt);
        sum1 += pp;
        float4 w = *(const float4*)&g_xw[src * 256 + 128 + c0];
        acc1.x += pp * w.x; acc1.y += pp * w.y;
        acc1.z += pp * w.z; acc1.w += pp * w.w;
    }

    // ---- bias + residual + LN ----
    float i0 = 1.f / sum0, i1 = 1.f / sum1;
    float4 bb0 = *(const float4*)&b0[c0];
    float4 bb1 = *(const float4*)&b1[c0];
    float4 x0 = *(const float4*)&x[n * 256 + c0];
    float4 x1 = *(const float4*)&x[n * 256 + 128 + c0];
    float vv[8];
    vv[0] = acc0.x * i0 + bb0.x + x0.x;
    vv[1] = acc0.y * i0 + bb0.y + x0.y;
    vv[2] = acc0.z * i0 + bb0.z + x0.z;
    vv[3] = acc0.w * i0 + bb0.w + x0.w;
    vv[4] = acc1.x * i1 + bb1.x + x1.x;
    vv[5] = acc1.y * i1 + bb1.y + x1.y;
    vv[6] = acc1.z * i1 + bb1.z + x1.z;
    vv[7] = acc1.w * i1 + bb1.w + x1.w;

    float s = 0.f, s2 = 0.f;
#pragma unroll
    for (int i = 0; i < 8; i++) { s += vv[i]; s2 += vv[i] * vv[i]; }
#pragma unroll
    for (int off = 16; off > 0; off >>= 1) {
        s  += __shfl_xor_sync(0xffffffffu, s, off);
        s2 += __shfl_xor_sync(0xffffffffu, s2, off);
    }
    float mean = s * (1.f / 256.f);
    float var  = s2 * (1.f / 256.f) - mean * mean;
    float rs   = rsqrtf(var + 1e-5f);

    float4 g0 = *(const float4*)&gamma[c0];
    float4 g1 = *(const float4*)&gamma[128 + c0];
    float4 be0 = *(const float4*)&beta[c0];
    float4 be1 = *(const float4*)&beta[128 + c0];
    float4 o0, o1;
    o0.x = (vv[0] - mean) * rs * g0.x + be0.x;
    o0.y = (vv[1] - mean) * rs * g0.y + be0.y;
    o0.z = (vv[2] - mean) * rs * g0.z + be0.z;
    o0.w = (vv[3] - mean) * rs * g0.w + be0.w;
    o1.x = (vv[4] - mean) * rs * g1.x + be1.x;
    o1.y = (vv[5] - mean) * rs * g1.y + be1.y;
    o1.z = (vv[6] - mean) * rs * g1.z + be1.z;
    o1.w = (vv[7] - mean) * rs * g1.w + be1.w;
    *(float4*)&out[n * 256 + c0]       = o0;
    *(float4*)&out[n * 256 + 128 + c0] = o1;
}

// ---------------- launch (single stream; overlap is proven harmful) ----------
extern "C" void kernel_launch(void* const* d_in, const int* in_sizes, int n_in,
                              void* d_out, int out_size) {
    const float* x     = (const float*)d_in[0];
    const int*   ei    = (const int*)d_in[1];
    const float* W0    = (const float*)d_in[2];
    const float* as0   = (const float*)d_in[3];
    const float* ad0   = (const float*)d_in[4];
    const float* b0    = (const float*)d_in[5];
    const float* W1    = (const float*)d_in[6];
    const float* as1   = (const float*)d_in[7];
    const float* ad1   = (const float*)d_in[8];
    const float* b1    = (const float*)d_in[9];
    const float* gamma = (const float*)d_in[10];
    const float* beta  = (const float*)d_in[11];
    float* out = (float*)d_out;

    const int* row = ei;
    const int* col = ei + N_EDGES;

    static bool attr_set = false;
    if (!attr_set) {
        cudaFuncSetAttribute(gemm_hmma_kernel,
                             cudaFuncAttributeMaxDynamicSharedMemorySize,
                             GEMM_SMEM_BYTES);
        attr_set = true;
    }

    zero_kernel<<<(TWO_N + 255) / 256, 256>>>();
    wsplit_kernel<<<256, 256>>>(W0, W1);
    gemm_hmma_kernel<<<dim3((N_NODES + 127) / 128, 2), 256, GEMM_SMEM_BYTES>>>(
        x, as0, ad0, as1, ad1);
    count0_kernel<<<(N_EDGES + 255) / 256, 256>>>(col);
    count1_kernel<<<(N_NODES + 255) / 256, 256>>>(col);
    scanA_kernel<<<SCAN_NBLK, SCAN_BLK>>>();
    scanB_kernel<<<1, 128>>>();
    scanC_kernel<<<SCAN_NBLK, SCAN_BLK>>>();
    scatter0_kernel<<<(N_EDGES + 255) / 256, 256>>>(row, col);
    scatter1_kernel<<<(N_NODES + 255) / 256, 256>>>(row, col);
    agg_ln_kernel<<<(N_NODES * 32 + 255) / 256, 256>>>(b0, b1, x, gamma, beta, out);
}

// round 15
// speedup vs baseline: 1.2271x; 1.1082x over previous
#include <cuda_runtime.h>
#include <cuda_bf16.h>
#include <cstdint>

#define N_NODES 50000
#define N_EDGES 800000
#define TWO_N   100000
#define TWO_E   1600000
#define SCAN_BLK 1024
#define SCAN_NBLK ((TWO_N + SCAN_BLK - 1) / SCAN_BLK)   // 98

// ---------------- scratch ----------------------------------------------------
__device__ __align__(16) float g_xw[N_NODES * 256];   // x @ [W0 | W1]
__device__ __align__(16) float g_att[N_NODES * 32];   // [s0(8) d0(8) s1(8) d1(8)]
__device__ __align__(16) __nv_bfloat16 g_Whi[256 * 256];  // [k][n] n: [W0|W1]
__device__ __align__(16) __nv_bfloat16 g_Wlo[256 * 256];
__device__ int   g_deg[TWO_N];     // [0,N): deg0; [N,2N): deg1 (collapsed)
__device__ int   g_off[TWO_N + 1];
__device__ int   g_cur[TWO_N];
__device__ int   g_srcarr[TWO_E];  // hop0: src; hop1: src | (weight<<16)
__device__ int   g_bsum[SCAN_NBLK];
__device__ int   g_bsum_scan[SCAN_NBLK];

__device__ __forceinline__ uint32_t smem_u32(const void* p) {
    uint32_t a;
    asm("{ .reg .u64 t; cvta.to.shared.u64 t, %1; cvt.u32.u64 %0, t; }"
        : "=r"(a) : "l"(p));
    return a;
}

// ---------------- W split kernel ---------------------------------------------
__global__ void wsplit_kernel(const float* __restrict__ W0,
                              const float* __restrict__ W1) {
    int i = blockIdx.x * 256 + threadIdx.x;
    int k = i >> 8, n = i & 255;
    float v = (n < 128) ? W0[k * 128 + n] : W1[k * 128 + (n - 128)];
    __nv_bfloat16 h = __float2bfloat16(v);
    g_Whi[i] = h;
    g_Wlo[i] = __float2bfloat16(v - __bfloat162float(h));
}

// ---------------- HMMA GEMM (split-bf16, 3 terms) + logits epilogue ----------
#define APAD 40
#define BPAD 136

__global__ __launch_bounds__(256) void gemm_hmma_kernel(
        const float* __restrict__ x,
        const float* __restrict__ as0, const float* __restrict__ ad0,
        const float* __restrict__ as1, const float* __restrict__ ad1) {
    __shared__ __nv_bfloat16 sAh[128][APAD];
    __shared__ __nv_bfloat16 sAl[128][APAD];
    __shared__ __nv_bfloat16 sBh[32][BPAD];
    __shared__ __nv_bfloat16 sBl[32][BPAD];

    int tid  = threadIdx.x;
    int wid  = tid >> 5;
    int lane = tid & 31;
    int m0   = blockIdx.x * 128;
    int half = blockIdx.y;
    int m0w  = (wid >> 1) * 32;
    int n0w  = (wid & 1) * 64;

    float acc[2][8][4];
#pragma unroll
    for (int a = 0; a < 2; a++)
#pragma unroll
        for (int b = 0; b < 8; b++)
#pragma unroll
            for (int c = 0; c < 4; c++) acc[a][b][c] = 0.f;

    int arow = tid >> 1, akb = (tid & 1) * 16;
    bool aok = (m0 + arow) < N_NODES;
    int bk = tid >> 3, bnb = (tid & 7) * 16;

    int a_roff = ((lane >> 3) & 1) * 8 + (lane & 7);
    int a_coff = ((lane >> 4) & 1) * 8;
    int b_koff = ((lane >> 3) & 1) * 8 + (lane & 7);
    int b_noff = ((lane >> 4) & 1) * 8;

    for (int kc = 0; kc < 8; kc++) {
        if (kc > 0) __syncthreads();
        {
            const float* src = x + (size_t)(m0 + arow) * 256 + kc * 32 + akb;
#pragma unroll
            for (int i = 0; i < 16; i += 4) {
                float4 v = aok ? *(const float4*)(src + i)
                               : make_float4(0.f, 0.f, 0.f, 0.f);
                float fv[4] = {v.x, v.y, v.z, v.w};
                uint32_t ph[2], pl[2];
#pragma unroll
                for (int j = 0; j < 2; j++) {
                    __nv_bfloat16 h0 = __float2bfloat16(fv[2*j]);
                    __nv_bfloat16 h1 = __float2bfloat16(fv[2*j+1]);
                    __nv_bfloat16 l0 = __float2bfloat16(fv[2*j]   - __bfloat162float(h0));
                    __nv_bfloat16 l1 = __float2bfloat16(fv[2*j+1] - __bfloat162float(h1));
                    ph[j] = (uint32_t)__bfloat16_as_ushort(h0)
                          | ((uint32_t)__bfloat16_as_ushort(h1) << 16);
                    pl[j] = (uint32_t)__bfloat16_as_ushort(l0)
                          | ((uint32_t)__bfloat16_as_ushort(l1) << 16);
                }
                *(uint2*)&sAh[arow][akb + i] = make_uint2(ph[0], ph[1]);
                *(uint2*)&sAl[arow][akb + i] = make_uint2(pl[0], pl[1]);
            }
        }
        {
            const __nv_bfloat16* wh = g_Whi + (size_t)(kc * 32 + bk) * 256 + half * 128 + bnb;
            const __nv_bfloat16* wl = g_Wlo + (size_t)(kc * 32 + bk) * 256 + half * 128 + bnb;
            uint4 vh0 = *(const uint4*)wh;
            uint4 vh1 = *(const uint4*)(wh + 8);
            uint4 vl0 = *(const uint4*)wl;
            uint4 vl1 = *(const uint4*)(wl + 8);
            *(uint4*)&sBh[bk][bnb]     = vh0;
            *(uint4*)&sBh[bk][bnb + 8] = vh1;
            *(uint4*)&sBl[bk][bnb]     = vl0;
            *(uint4*)&sBl[bk][bnb + 8] = vl1;
        }
        __syncthreads();

#pragma unroll
        for (int ks = 0; ks < 2; ks++) {
            int k0 = ks * 16;
            uint32_t ah[2][4], al[2][4], bb[4][4];
#pragma unroll
            for (int mt = 0; mt < 2; mt++) {
                uint32_t adrh = smem_u32(&sAh[m0w + mt * 16 + a_roff][k0 + a_coff]);
                asm volatile("ldmatrix.sync.aligned.m8n8.x4.shared.b16 {%0,%1,%2,%3}, [%4];"
                    : "=r"(ah[mt][0]), "=r"(ah[mt][1]), "=r"(ah[mt][2]), "=r"(ah[mt][3])
                    : "r"(adrh));
                uint32_t adrl = smem_u32(&sAl[m0w + mt * 16 + a_roff][k0 + a_coff]);
                asm volatile("ldmatrix.sync.aligned.m8n8.x4.shared.b16 {%0,%1,%2,%3}, [%4];"
                    : "=r"(al[mt][0]), "=r"(al[mt][1]), "=r"(al[mt][2]), "=r"(al[mt][3])
                    : "r"(adrl));
            }
#pragma unroll
            for (int p = 0; p < 4; p++) {
                uint32_t adr = smem_u32(&sBh[k0 + b_koff][n0w + p * 16 + b_noff]);
                asm volatile("ldmatrix.sync.aligned.m8n8.x4.trans.shared.b16 {%0,%1,%2,%3}, [%4];"
                    : "=r"(bb[p][0]), "=r"(bb[p][1]), "=r"(bb[p][2]), "=r"(bb[p][3])
                    : "r"(adr));
            }
#pragma unroll
            for (int mt = 0; mt < 2; mt++)
#pragma unroll
                for (int nt = 0; nt < 8; nt++) {
                    uint32_t b0 = bb[nt >> 1][(nt & 1) * 2];
                    uint32_t b1 = bb[nt >> 1][(nt & 1) * 2 + 1];
                    float* d = acc[mt][nt];
                    asm volatile(
                        "mma.sync.aligned.m16n8k16.row.col.f32.bf16.bf16.f32 "
                        "{%0,%1,%2,%3}, {%4,%5,%6,%7}, {%8,%9}, {%0,%1,%2,%3};"
                        : "+f"(d[0]), "+f"(d[1]), "+f"(d[2]), "+f"(d[3])
                        : "r"(ah[mt][0]), "r"(ah[mt][1]), "r"(ah[mt][2]), "r"(ah[mt][3]),
                          "r"(b0), "r"(b1));
                    asm volatile(
                        "mma.sync.aligned.m16n8k16.row.col.f32.bf16.bf16.f32 "
                        "{%0,%1,%2,%3}, {%4,%5,%6,%7}, {%8,%9}, {%0,%1,%2,%3};"
                        : "+f"(d[0]), "+f"(d[1]), "+f"(d[2]), "+f"(d[3])
                        : "r"(al[mt][0]), "r"(al[mt][1]), "r"(al[mt][2]), "r"(al[mt][3]),
                          "r"(b0), "r"(b1));
                }
#pragma unroll
            for (int p = 0; p < 4; p++) {
                uint32_t adr = smem_u32(&sBl[k0 + b_koff][n0w + p * 16 + b_noff]);
                asm volatile("ldmatrix.sync.aligned.m8n8.x4.trans.shared.b16 {%0,%1,%2,%3}, [%4];"
                    : "=r"(bb[p][0]), "=r"(bb[p][1]), "=r"(bb[p][2]), "=r"(bb[p][3])
                    : "r"(adr));
            }
#pragma unroll
            for (int mt = 0; mt < 2; mt++)
#pragma unroll
                for (int nt = 0; nt < 8; nt++) {
                    uint32_t b0 = bb[nt >> 1][(nt & 1) * 2];
                    uint32_t b1 = bb[nt >> 1][(nt & 1) * 2 + 1];
                    float* d = acc[mt][nt];
                    asm volatile(
                        "mma.sync.aligned.m16n8k16.row.col.f32.bf16.bf16.f32 "
                        "{%0,%1,%2,%3}, {%4,%5,%6,%7}, {%8,%9}, {%0,%1,%2,%3};"
                        : "+f"(d[0]), "+f"(d[1]), "+f"(d[2]), "+f"(d[3])
                        : "r"(ah[mt][0]), "r"(ah[mt][1]), "r"(ah[mt][2]), "r"(ah[mt][3]),
                          "r"(b0), "r"(b1));
                }
        }
    }

    // ---- epilogue: store xw + attention logits ----
#pragma unroll
    for (int mt = 0; mt < 2; mt++) {
        int r0 = m0 + m0w + mt * 16 + (lane >> 2);
        int r1 = r0 + 8;
        bool ok0 = r0 < N_NODES, ok1 = r1 < N_NODES;
#pragma unroll
        for (int nt = 0; nt < 8; nt++) {
            int col = half * 128 + n0w + nt * 8 + (lane & 3) * 2;
            if (ok0) *(float2*)&g_xw[(size_t)r0 * 256 + col] =
                make_float2(acc[mt][nt][0], acc[mt][nt][1]);
            if (ok1) *(float2*)&g_xw[(size_t)r1 * 256 + col] =
                make_float2(acc[mt][nt][2], acc[mt][nt][3]);
        }
    }

    const float* asv = half ? as1 : as0;
    const float* adv = half ? ad1 : ad0;
    float asr[16], adr_[16];
#pragma unroll
    for (int nt = 0; nt < 8; nt++) {
        int c = n0w + nt * 8 + (lane & 3) * 2;
        asr[nt * 2]     = asv[c];
        asr[nt * 2 + 1] = asv[c + 1];
        adr_[nt * 2]     = adv[c];
        adr_[nt * 2 + 1] = adv[c + 1];
    }
#pragma unroll
    for (int mt = 0; mt < 2; mt++) {
#pragma unroll
        for (int rh = 0; rh < 2; rh++) {
            float ps[4] = {0.f, 0.f, 0.f, 0.f};
            float pd[4] = {0.f, 0.f, 0.f, 0.f};
#pragma unroll
            for (int nt = 0; nt < 8; nt++) {
                int h = nt >> 1;
                float a0 = acc[mt][nt][rh * 2];
                float a1 = acc[mt][nt][rh * 2 + 1];
                ps[h] += a0 * asr[nt * 2] + a1 * asr[nt * 2 + 1];
                pd[h] += a0 * adr_[nt * 2] + a1 * adr_[nt * 2 + 1];
            }
#pragma unroll
            for (int off = 1; off < 4; off <<= 1) {
#pragma unroll
                for (int h = 0; h < 4; h++) {
                    ps[h] += __shfl_xor_sync(0xffffffffu, ps[h], off);
                    pd[h] += __shfl_xor_sync(0xffffffffu, pd[h], off);
                }
            }
            int r = m0 + m0w + mt * 16 + rh * 8 + (lane >> 2);
            if ((lane & 3) == 0 && r < N_NODES) {
#pragma unroll
                for (int h = 0; h < 4; h++) {
                    int gh = (n0w >> 4) + h;
                    g_att[r * 32 + half * 16 + gh]     = ps[h];
                    g_att[r * 32 + half * 16 + 8 + gh] = pd[h];
                }
            }
        }
    }
}

// ---------------- zero degree counters ---------------------------------------
__global__ void zero_kernel() {
    int i = blockIdx.x * blockDim.x + threadIdx.x;
    if (i < TWO_N) g_deg[i] = 0;
}

// ---------------- count0: hop-0 in-degrees -----------------------------------
__global__ void count0_kernel(const int* __restrict__ col) {
    int e = blockIdx.x * blockDim.x + threadIdx.x;
    if (e >= N_EDGES) return;
    atomicAdd(&g_deg[col[e]], 1);
}

// ---------------- count1: collapsed hop-1 degrees ----------------------------
__global__ void count1_kernel(const int* __restrict__ col) {
    int c = blockIdx.x * blockDim.x + threadIdx.x;
    if (c >= N_NODES) return;
    if (g_deg[c] > 0) atomicAdd(&g_deg[N_NODES + col[c]], 1);
}

// ---------------- exclusive scan (3 stages) ----------------------------------
__global__ void scanA_kernel() {
    __shared__ int sh[SCAN_BLK];
    int t = threadIdx.x;
    int i = blockIdx.x * SCAN_BLK + t;
    int v = (i < TWO_N) ? g_deg[i] : 0;
    sh[t] = v;
    __syncthreads();
    for (int off = 1; off < SCAN_BLK; off <<= 1) {
        int add = (t >= off) ? sh[t - off] : 0;
        __syncthreads();
        sh[t] += add;
        __syncthreads();
    }
    if (i < TWO_N) g_off[i] = sh[t] - v;
    if (t == SCAN_BLK - 1) g_bsum[blockIdx.x] = sh[SCAN_BLK - 1];
}

__global__ void scanB_kernel() {
    __shared__ int sh[128];
    int t = threadIdx.x;
    int v = (t < SCAN_NBLK) ? g_bsum[t] : 0;
    sh[t] = v;
    __syncthreads();
    for (int off = 1; off < 128; off <<= 1) {
        int add = (t >= off) ? sh[t - off] : 0;
        __syncthreads();
        sh[t] += add;
        __syncthreads();
    }
    if (t < SCAN_NBLK) g_bsum_scan[t] = sh[t] - v;
}

__global__ void scanC_kernel() {
    int i = blockIdx.x * SCAN_BLK + threadIdx.x;
    if (i < TWO_N) {
        int v = g_off[i] + g_bsum_scan[blockIdx.x];
        g_off[i] = v;
        g_cur[i] = v;
        if (i == TWO_N - 1) g_off[TWO_N] = v + g_deg[i];
    }
}

// ---------------- scatter0: hop-0 edges --------------------------------------
__global__ void scatter0_kernel(const int* __restrict__ row,
                                const int* __restrict__ col) {
    int e = blockIdx.x * blockDim.x + threadIdx.x;
    if (e >= N_EDGES) return;
    int p = atomicAdd(&g_cur[col[e]], 1);
    g_srcarr[p] = row[e];
}

// ---------------- scatter1: collapsed hop-1 entries (src | weight<<16) -------
__global__ void scatter1_kernel(const int* __restrict__ row,
                                const int* __restrict__ col) {
    int c = blockIdx.x * blockDim.x + threadIdx.x;
    if (c >= N_NODES) return;
    int w = g_deg[c];
    if (w <= 0) return;
    int p = atomicAdd(&g_cur[N_NODES + col[c]], 1);
    g_srcarr[p] = row[c] | (w << 16);
}

// ---------------- fused aggregation + residual + LayerNorm -------------------
// warp per node. Hop-0 edge loop x4-batched: 4 independent src loads, then
// 4 att loads, then 4 xw loads -> MLP 4 on the L2 chain. Hop-1 is the
// collapsed weighted list (~1 entry/node avg), left simple.
__global__ void agg_ln_kernel(const float* __restrict__ b0,
                              const float* __restrict__ b1,
                              const float* __restrict__ x,
                              const float* __restrict__ gamma,
                              const float* __restrict__ beta,
                              float* __restrict__ out) {
    int n = (blockIdx.x * blockDim.x + threadIdx.x) >> 5;
    if (n >= N_NODES) return;
    int lane = threadIdx.x & 31;
    int head = lane >> 2;
    int c0 = lane * 4;

    // ---- hop 0 ----
    float ad = g_att[n * 32 + 8 + head];
    float t  = g_att[n * 32 + head] + ad;
    t = (t > 0.f) ? t : 0.2f * t;
    float p = __expf(t);
    float sum0 = p;
    float4 v = *(const float4*)&g_xw[n * 256 + c0];
    float4 acc0 = make_float4(p * v.x, p * v.y, p * v.z, p * v.w);
    {
        int jb = g_off[n], je = g_off[n + 1];
        int j = jb;
        for (; j + 4 <= je; j += 4) {
            int s0 = g_srcarr[j];
            int s1 = g_srcarr[j + 1];
            int s2 = g_srcarr[j + 2];
            int s3 = g_srcarr[j + 3];
            float t0 = g_att[s0 * 32 + head];
            float t1 = g_att[s1 * 32 + head];
            float t2 = g_att[s2 * 32 + head];
            float t3 = g_att[s3 * 32 + head];
            float4 w0 = *(const float4*)&g_xw[s0 * 256 + c0];
            float4 w1 = *(const float4*)&g_xw[s1 * 256 + c0];
            float4 w2 = *(const float4*)&g_xw[s2 * 256 + c0];
            float4 w3 = *(const float4*)&g_xw[s3 * 256 + c0];
            t0 += ad; t0 = (t0 > 0.f) ? t0 : 0.2f * t0;
            t1 += ad; t1 = (t1 > 0.f) ? t1 : 0.2f * t1;
            t2 += ad; t2 = (t2 > 0.f) ? t2 : 0.2f * t2;
            t3 += ad; t3 = (t3 > 0.f) ? t3 : 0.2f * t3;
            float p0 = __expf(t0), p1 = __expf(t1);
            float p2 = __expf(t2), p3 = __expf(t3);
            sum0 += (p0 + p1) + (p2 + p3);
            acc0.x += p0 * w0.x + p1 * w1.x + p2 * w2.x + p3 * w3.x;
            acc0.y += p0 * w0.y + p1 * w1.y + p2 * w2.y + p3 * w3.y;
            acc0.z += p0 * w0.z + p1 * w1.z + p2 * w2.z + p3 * w3.z;
            acc0.w += p0 * w0.w + p1 * w1.w + p2 * w2.w + p3 * w3.w;
        }
        for (; j < je; j++) {
            int src = g_srcarr[j];
            float tt = g_att[src * 32 + head] + ad;
            tt = (tt > 0.f) ? tt : 0.2f * tt;
            float pp = __expf(tt);
            sum0 += pp;
            float4 w = *(const float4*)&g_xw[src * 256 + c0];
            acc0.x += pp * w.x; acc0.y += pp * w.y;
            acc0.z += pp * w.z; acc0.w += pp * w.w;
        }
    }

    // ---- hop 1 (collapsed weighted entries; self doubled) ----
    ad = g_att[n * 32 + 24 + head];
    t  = g_att[n * 32 + 16 + head] + ad;
    t = (t > 0.f) ? t : 0.2f * t;
    p = 2.0f * __expf(t);
    float sum1 = p;
    v = *(const float4*)&g_xw[n * 256 + 128 + c0];
    float4 acc1 = make_float4(p * v.x, p * v.y, p * v.z, p * v.w);
    int je1 = g_off[N_NODES + n + 1];
    for (int j = g_off[N_NODES + n]; j < je1; j++) {
        int ent = g_srcarr[j];
        int src = ent & 0xFFFF;
        float wgt = (float)(ent >> 16);
        float tt = g_att[src * 32 + 16 + head] + ad;
        tt = (tt > 0.f) ? tt : 0.2f * tt;
        float pp = wgt * __expf(tt);
        sum1 += pp;
        float4 w = *(const float4*)&g_xw[src * 256 + 128 + c0];
        acc1.x += pp * w.x; acc1.y += pp * w.y;
        acc1.z += pp * w.z; acc1.w += pp * w.w;
    }

    // ---- bias + residual + LN ----
    float i0 = 1.f / sum0, i1 = 1.f / sum1;
    float4 bb0 = *(const float4*)&b0[c0];
    float4 bb1 = *(const float4*)&b1[c0];
    float4 x0 = *(const float4*)&x[n * 256 + c0];
    float4 x1 = *(const float4*)&x[n * 256 + 128 + c0];
    float vv[8];
    vv[0] = acc0.x * i0 + bb0.x + x0.x;
    vv[1] = acc0.y * i0 + bb0.y + x0.y;
    vv[2] = acc0.z * i0 + bb0.z + x0.z;
    vv[3] = acc0.w * i0 + bb0.w + x0.w;
    vv[4] = acc1.x * i1 + bb1.x + x1.x;
    vv[5] = acc1.y * i1 + bb1.y + x1.y;
    vv[6] = acc1.z * i1 + bb1.z + x1.z;
    vv[7] = acc1.w * i1 + bb1.w + x1.w;

    float s = 0.f, s2 = 0.f;
#pragma unroll
    for (int i = 0; i < 8; i++) { s += vv[i]; s2 += vv[i] * vv[i]; }
#pragma unroll
    for (int off = 16; off > 0; off >>= 1) {
        s  += __shfl_xor_sync(0xffffffffu, s, off);
        s2 += __shfl_xor_sync(0xffffffffu, s2, off);
    }
    float mean = s * (1.f / 256.f);
    float var  = s2 * (1.f / 256.f) - mean * mean;
    float rs   = rsqrtf(var + 1e-5f);

    float4 g0 = *(const float4*)&gamma[c0];
    float4 g1 = *(const float4*)&gamma[128 + c0];
    float4 be0 = *(const float4*)&beta[c0];
    float4 be1 = *(const float4*)&beta[128 + c0];
    float4 o0, o1;
    o0.x = (vv[0] - mean) * rs * g0.x + be0.x;
    o0.y = (vv[1] - mean) * rs * g0.y + be0.y;
    o0.z = (vv[2] - mean) * rs * g0.z + be0.z;
    o0.w = (vv[3] - mean) * rs * g0.w + be0.w;
    o1.x = (vv[4] - mean) * rs * g1.x + be1.x;
    o1.y = (vv[5] - mean) * rs * g1.y + be1.y;
    o1.z = (vv[6] - mean) * rs * g1.z + be1.z;
    o1.w = (vv[7] - mean) * rs * g1.w + be1.w;
    *(float4*)&out[n * 256 + c0]       = o0;
    *(float4*)&out[n * 256 + 128 + c0] = o1;
}

// ---------------- launch (single stream) -------------------------------------
extern "C" void kernel_launch(void* const* d_in, const int* in_sizes, int n_in,
                              void* d_out, int out_size) {
    const float* x     = (const float*)d_in[0];
    const int*   ei    = (const int*)d_in[1];
    const float* W0    = (const float*)d_in[2];
    const float* as0   = (const float*)d_in[3];
    const float* ad0   = (const float*)d_in[4];
    const float* b0    = (const float*)d_in[5];
    const float* W1    = (const float*)d_in[6];
    const float* as1   = (const float*)d_in[7];
    const float* ad1   = (const float*)d_in[8];
    const float* b1    = (const float*)d_in[9];
    const float* gamma = (const float*)d_in[10];
    const float* beta  = (const float*)d_in[11];
    float* out = (float*)d_out;

    const int* row = ei;
    const int* col = ei + N_EDGES;

    zero_kernel<<<(TWO_N + 255) / 256, 256>>>();
    wsplit_kernel<<<256, 256>>>(W0, W1);
    gemm_hmma_kernel<<<dim3((N_NODES + 127) / 128, 2), 256>>>(x, as0, ad0, as1, ad1);
    count0_kernel<<<(N_EDGES + 255) / 256, 256>>>(col);
    count1_kernel<<<(N_NODES + 255) / 256, 256>>>(col);
    scanA_kernel<<<SCAN_NBLK, SCAN_BLK>>>();
    scanB_kernel<<<1, 128>>>();
    scanC_kernel<<<SCAN_NBLK, SCAN_BLK>>>();
    scatter0_kernel<<<(N_EDGES + 255) / 256, 256>>>(row, col);
    scatter1_kernel<<<(N_NODES + 255) / 256, 256>>>(row, col);
    agg_ln_kernel<<<(N_NODES * 32 + 255) / 256, 256>>>(b0, b1, x, gamma, beta, out);
}

// round 16
// speedup vs baseline: 1.2421x; 1.0122x over previous
#include <cuda_runtime.h>
#include <cuda_bf16.h>
#include <cstdint>

#define N_NODES 50000
#define N_EDGES 800000
#define TWO_N   100000
#define TWO_E   1600000
#define SCAN_BLK 1024
#define SCAN_NBLK ((TWO_N + SCAN_BLK - 1) / SCAN_BLK)   // 98

// ---------------- scratch ----------------------------------------------------
__device__ __align__(16) float g_xw[N_NODES * 256];   // x @ [W0 | W1]
__device__ __align__(16) float g_att[N_NODES * 32];   // [s0(8) d0(8) s1(8) d1(8)]
__device__ __align__(16) __nv_bfloat16 g_Whi[256 * 256];  // [k][n] n: [W0|W1]
__device__ __align__(16) __nv_bfloat16 g_Wlo[256 * 256];
__device__ int   g_deg[TWO_N];     // [0,N): deg0; [N,2N): deg1 (collapsed)
__device__ int   g_off[TWO_N + 1];
__device__ int   g_cur[TWO_N];
__device__ int   g_srcarr[TWO_E];  // hop0: src; hop1: src | (weight<<16)
__device__ int   g_bsum[SCAN_NBLK];
__device__ int   g_bsum_scan[SCAN_NBLK];

__device__ __forceinline__ uint32_t smem_u32(const void* p) {
    uint32_t a;
    asm("{ .reg .u64 t; cvta.to.shared.u64 t, %1; cvt.u32.u64 %0, t; }"
        : "=r"(a) : "l"(p));
    return a;
}

// ---------------- W split kernel ---------------------------------------------
__global__ void wsplit_kernel(const float* __restrict__ W0,
                              const float* __restrict__ W1) {
    int i = blockIdx.x * 256 + threadIdx.x;
    int k = i >> 8, n = i & 255;
    float v = (n < 128) ? W0[k * 128 + n] : W1[k * 128 + (n - 128)];
    __nv_bfloat16 h = __float2bfloat16(v);
    g_Whi[i] = h;
    g_Wlo[i] = __float2bfloat16(v - __bfloat162float(h));
}

// ---------------- HMMA GEMM (split-bf16, 3 terms) + logits epilogue ----------
#define APAD 40
#define BPAD 136

__global__ __launch_bounds__(256) void gemm_hmma_kernel(
        const float* __restrict__ x,
        const float* __restrict__ as0, const float* __restrict__ ad0,
        const float* __restrict__ as1, const float* __restrict__ ad1) {
    __shared__ __nv_bfloat16 sAh[128][APAD];
    __shared__ __nv_bfloat16 sAl[128][APAD];
    __shared__ __nv_bfloat16 sBh[32][BPAD];
    __shared__ __nv_bfloat16 sBl[32][BPAD];

    int tid  = threadIdx.x;
    int wid  = tid >> 5;
    int lane = tid & 31;
    int m0   = blockIdx.x * 128;
    int half = blockIdx.y;
    int m0w  = (wid >> 1) * 32;
    int n0w  = (wid & 1) * 64;

    float acc[2][8][4];
#pragma unroll
    for (int a = 0; a < 2; a++)
#pragma unroll
        for (int b = 0; b < 8; b++)
#pragma unroll
            for (int c = 0; c < 4; c++) acc[a][b][c] = 0.f;

    int arow = tid >> 1, akb = (tid & 1) * 16;
    bool aok = (m0 + arow) < N_NODES;
    int bk = tid >> 3, bnb = (tid & 7) * 16;

    int a_roff = ((lane >> 3) & 1) * 8 + (lane & 7);
    int a_coff = ((lane >> 4) & 1) * 8;
    int b_koff = ((lane >> 3) & 1) * 8 + (lane & 7);
    int b_noff = ((lane >> 4) & 1) * 8;

    for (int kc = 0; kc < 8; kc++) {
        if (kc > 0) __syncthreads();
        {
            const float* src = x + (size_t)(m0 + arow) * 256 + kc * 32 + akb;
#pragma unroll
            for (int i = 0; i < 16; i += 4) {
                float4 v = aok ? *(const float4*)(src + i)
                               : make_float4(0.f, 0.f, 0.f, 0.f);
                float fv[4] = {v.x, v.y, v.z, v.w};
                uint32_t ph[2], pl[2];
#pragma unroll
                for (int j = 0; j < 2; j++) {
                    __nv_bfloat16 h0 = __float2bfloat16(fv[2*j]);
                    __nv_bfloat16 h1 = __float2bfloat16(fv[2*j+1]);
                    __nv_bfloat16 l0 = __float2bfloat16(fv[2*j]   - __bfloat162float(h0));
                    __nv_bfloat16 l1 = __float2bfloat16(fv[2*j+1] - __bfloat162float(h1));
                    ph[j] = (uint32_t)__bfloat16_as_ushort(h0)
                          | ((uint32_t)__bfloat16_as_ushort(h1) << 16);
                    pl[j] = (uint32_t)__bfloat16_as_ushort(l0)
                          | ((uint32_t)__bfloat16_as_ushort(l1) << 16);
                }
                *(uint2*)&sAh[arow][akb + i] = make_uint2(ph[0], ph[1]);
                *(uint2*)&sAl[arow][akb + i] = make_uint2(pl[0], pl[1]);
            }
        }
        {
            const __nv_bfloat16* wh = g_Whi + (size_t)(kc * 32 + bk) * 256 + half * 128 + bnb;
            const __nv_bfloat16* wl = g_Wlo + (size_t)(kc * 32 + bk) * 256 + half * 128 + bnb;
            uint4 vh0 = *(const uint4*)wh;
            uint4 vh1 = *(const uint4*)(wh + 8);
            uint4 vl0 = *(const uint4*)wl;
            uint4 vl1 = *(const uint4*)(wl + 8);
            *(uint4*)&sBh[bk][bnb]     = vh0;
            *(uint4*)&sBh[bk][bnb + 8] = vh1;
            *(uint4*)&sBl[bk][bnb]     = vl0;
            *(uint4*)&sBl[bk][bnb + 8] = vl1;
        }
        __syncthreads();

#pragma unroll
        for (int ks = 0; ks < 2; ks++) {
            int k0 = ks * 16;
            uint32_t ah[2][4], al[2][4], bb[4][4];
#pragma unroll
            for (int mt = 0; mt < 2; mt++) {
                uint32_t adrh = smem_u32(&sAh[m0w + mt * 16 + a_roff][k0 + a_coff]);
                asm volatile("ldmatrix.sync.aligned.m8n8.x4.shared.b16 {%0,%1,%2,%3}, [%4];"
                    : "=r"(ah[mt][0]), "=r"(ah[mt][1]), "=r"(ah[mt][2]), "=r"(ah[mt][3])
                    : "r"(adrh));
                uint32_t adrl = smem_u32(&sAl[m0w + mt * 16 + a_roff][k0 + a_coff]);
                asm volatile("ldmatrix.sync.aligned.m8n8.x4.shared.b16 {%0,%1,%2,%3}, [%4];"
                    : "=r"(al[mt][0]), "=r"(al[mt][1]), "=r"(al[mt][2]), "=r"(al[mt][3])
                    : "r"(adrl));
            }
#pragma unroll
            for (int p = 0; p < 4; p++) {
                uint32_t adr = smem_u32(&sBh[k0 + b_koff][n0w + p * 16 + b_noff]);
                asm volatile("ldmatrix.sync.aligned.m8n8.x4.trans.shared.b16 {%0,%1,%2,%3}, [%4];"
                    : "=r"(bb[p][0]), "=r"(bb[p][1]), "=r"(bb[p][2]), "=r"(bb[p][3])
                    : "r"(adr));
            }
#pragma unroll
            for (int mt = 0; mt < 2; mt++)
#pragma unroll
                for (int nt = 0; nt < 8; nt++) {
                    uint32_t b0 = bb[nt >> 1][(nt & 1) * 2];
                    uint32_t b1 = bb[nt >> 1][(nt & 1) * 2 + 1];
                    float* d = acc[mt][nt];
                    asm volatile(
                        "mma.sync.aligned.m16n8k16.row.col.f32.bf16.bf16.f32 "
                        "{%0,%1,%2,%3}, {%4,%5,%6,%7}, {%8,%9}, {%0,%1,%2,%3};"
                        : "+f"(d[0]), "+f"(d[1]), "+f"(d[2]), "+f"(d[3])
                        : "r"(ah[mt][0]), "r"(ah[mt][1]), "r"(ah[mt][2]), "r"(ah[mt][3]),
                          "r"(b0), "r"(b1));
                    asm volatile(
                        "mma.sync.aligned.m16n8k16.row.col.f32.bf16.bf16.f32 "
                        "{%0,%1,%2,%3}, {%4,%5,%6,%7}, {%8,%9}, {%0,%1,%2,%3};"
                        : "+f"(d[0]), "+f"(d[1]), "+f"(d[2]), "+f"(d[3])
                        : "r"(al[mt][0]), "r"(al[mt][1]), "r"(al[mt][2]), "r"(al[mt][3]),
                          "r"(b0), "r"(b1));
                }
#pragma unroll
            for (int p = 0; p < 4; p++) {
                uint32_t adr = smem_u32(&sBl[k0 + b_koff][n0w + p * 16 + b_noff]);
                asm volatile("ldmatrix.sync.aligned.m8n8.x4.trans.shared.b16 {%0,%1,%2,%3}, [%4];"
                    : "=r"(bb[p][0]), "=r"(bb[p][1]), "=r"(bb[p][2]), "=r"(bb[p][3])
                    : "r"(adr));
            }
#pragma unroll
            for (int mt = 0; mt < 2; mt++)
#pragma unroll
                for (int nt = 0; nt < 8; nt++) {
                    uint32_t b0 = bb[nt >> 1][(nt & 1) * 2];
                    uint32_t b1 = bb[nt >> 1][(nt & 1) * 2 + 1];
                    float* d = acc[mt][nt];
                    asm volatile(
                        "mma.sync.aligned.m16n8k16.row.col.f32.bf16.bf16.f32 "
                        "{%0,%1,%2,%3}, {%4,%5,%6,%7}, {%8,%9}, {%0,%1,%2,%3};"
                        : "+f"(d[0]), "+f"(d[1]), "+f"(d[2]), "+f"(d[3])
                        : "r"(ah[mt][0]), "r"(ah[mt][1]), "r"(ah[mt][2]), "r"(ah[mt][3]),
                          "r"(b0), "r"(b1));
                }
        }
    }

    // ---- epilogue: store xw + attention logits ----
#pragma unroll
    for (int mt = 0; mt < 2; mt++) {
        int r0 = m0 + m0w + mt * 16 + (lane >> 2);
        int r1 = r0 + 8;
        bool ok0 = r0 < N_NODES, ok1 = r1 < N_NODES;
#pragma unroll
        for (int nt = 0; nt < 8; nt++) {
            int col = half * 128 + n0w + nt * 8 + (lane & 3) * 2;
            if (ok0) *(float2*)&g_xw[(size_t)r0 * 256 + col] =
                make_float2(acc[mt][nt][0], acc[mt][nt][1]);
            if (ok1) *(float2*)&g_xw[(size_t)r1 * 256 + col] =
                make_float2(acc[mt][nt][2], acc[mt][nt][3]);
        }
    }

    const float* asv = half ? as1 : as0;
    const float* adv = half ? ad1 : ad0;
    float asr[16], adr_[16];
#pragma unroll
    for (int nt = 0; nt < 8; nt++) {
        int c = n0w + nt * 8 + (lane & 3) * 2;
        asr[nt * 2]     = asv[c];
        asr[nt * 2 + 1] = asv[c + 1];
        adr_[nt * 2]     = adv[c];
        adr_[nt * 2 + 1] = adv[c + 1];
    }
#pragma unroll
    for (int mt = 0; mt < 2; mt++) {
#pragma unroll
        for (int rh = 0; rh < 2; rh++) {
            float ps[4] = {0.f, 0.f, 0.f, 0.f};
            float pd[4] = {0.f, 0.f, 0.f, 0.f};
#pragma unroll
            for (int nt = 0; nt < 8; nt++) {
                int h = nt >> 1;
                float a0 = acc[mt][nt][rh * 2];
                float a1 = acc[mt][nt][rh * 2 + 1];
                ps[h] += a0 * asr[nt * 2] + a1 * asr[nt * 2 + 1];
                pd[h] += a0 * adr_[nt * 2] + a1 * adr_[nt * 2 + 1];
            }
#pragma unroll
            for (int off = 1; off < 4; off <<= 1) {
#pragma unroll
                for (int h = 0; h < 4; h++) {
                    ps[h] += __shfl_xor_sync(0xffffffffu, ps[h], off);
                    pd[h] += __shfl_xor_sync(0xffffffffu, pd[h], off);
                }
            }
            int r = m0 + m0w + mt * 16 + rh * 8 + (lane >> 2);
            if ((lane & 3) == 0 && r < N_NODES) {
#pragma unroll
                for (int h = 0; h < 4; h++) {
                    int gh = (n0w >> 4) + h;
                    g_att[r * 32 + half * 16 + gh]     = ps[h];
                    g_att[r * 32 + half * 16 + 8 + gh] = pd[h];
                }
            }
        }
    }
}

// ---------------- zero degree counters ---------------------------------------
__global__ void zero_kernel() {
    int i = blockIdx.x * blockDim.x + threadIdx.x;
    if (i < TWO_N) g_deg[i] = 0;
}

// ---------------- count0: hop-0 in-degrees -----------------------------------
__global__ void count0_kernel(const int* __restrict__ col) {
    int e = blockIdx.x * blockDim.x + threadIdx.x;
    if (e >= N_EDGES) return;
    atomicAdd(&g_deg[col[e]], 1);
}

// ---------------- count1: collapsed hop-1 degrees ----------------------------
__global__ void count1_kernel(const int* __restrict__ col) {
    int c = blockIdx.x * blockDim.x + threadIdx.x;
    if (c >= N_NODES) return;
    if (g_deg[c] > 0) atomicAdd(&g_deg[N_NODES + col[c]], 1);
}

// ---------------- exclusive scan (3 stages) ----------------------------------
__global__ void scanA_kernel() {
    __shared__ int sh[SCAN_BLK];
    int t = threadIdx.x;
    int i = blockIdx.x * SCAN_BLK + t;
    int v = (i < TWO_N) ? g_deg[i] : 0;
    sh[t] = v;
    __syncthreads();
    for (int off = 1; off < SCAN_BLK; off <<= 1) {
        int add = (t >= off) ? sh[t - off] : 0;
        __syncthreads();
        sh[t] += add;
        __syncthreads();
    }
    if (i < TWO_N) g_off[i] = sh[t] - v;
    if (t == SCAN_BLK - 1) g_bsum[blockIdx.x] = sh[SCAN_BLK - 1];
}

__global__ void scanB_kernel() {
    __shared__ int sh[128];
    int t = threadIdx.x;
    int v = (t < SCAN_NBLK) ? g_bsum[t] : 0;
    sh[t] = v;
    __syncthreads();
    for (int off = 1; off < 128; off <<= 1) {
        int add = (t >= off) ? sh[t - off] : 0;
        __syncthreads();
        sh[t] += add;
        __syncthreads();
    }
    if (t < SCAN_NBLK) g_bsum_scan[t] = sh[t] - v;
}

__global__ void scanC_kernel() {
    int i = blockIdx.x * SCAN_BLK + threadIdx.x;
    if (i < TWO_N) {
        int v = g_off[i] + g_bsum_scan[blockIdx.x];
        g_off[i] = v;
        g_cur[i] = v;
        if (i == TWO_N - 1) g_off[TWO_N] = v + g_deg[i];
    }
}

// ---------------- scatter (merged): hop-0 edges + collapsed hop-1 entries ----
__global__ void scatter_kernel(const int* __restrict__ row,
                               const int* __restrict__ col) {
    int i = blockIdx.x * blockDim.x + threadIdx.x;
    if (i < N_EDGES) {
        int p = atomicAdd(&g_cur[col[i]], 1);
        g_srcarr[p] = row[i];
    } else {
        int c = i - N_EDGES;
        if (c >= N_NODES) return;
        int w = g_deg[c];
        if (w <= 0) return;
        int p = atomicAdd(&g_cur[N_NODES + col[c]], 1);
        g_srcarr[p] = row[c] | (w << 16);
    }
}

// ---------------- fused aggregation + residual + LayerNorm -------------------
__global__ void agg_ln_kernel(const float* __restrict__ b0,
                              const float* __restrict__ b1,
                              const float* __restrict__ x,
                              const float* __restrict__ gamma,
                              const float* __restrict__ beta,
                              float* __restrict__ out) {
    int n = (blockIdx.x * blockDim.x + threadIdx.x) >> 5;
    if (n >= N_NODES) return;
    int lane = threadIdx.x & 31;
    int head = lane >> 2;
    int c0 = lane * 4;

    // ---- hop 0 ----
    float ad = g_att[n * 32 + 8 + head];
    float t  = g_att[n * 32 + head] + ad;
    t = (t > 0.f) ? t : 0.2f * t;
    float p = __expf(t);
    float sum0 = p;
    float4 v = *(const float4*)&g_xw[n * 256 + c0];
    float4 acc0 = make_float4(p * v.x, p * v.y, p * v.z, p * v.w);
    int je = g_off[n + 1];
    for (int j = g_off[n]; j < je; j++) {
        int src = g_srcarr[j];
        float tt = g_att[src * 32 + head] + ad;
        tt = (tt > 0.f) ? tt : 0.2f * tt;
        float pp = __expf(tt);
        sum0 += pp;
        float4 w = *(const float4*)&g_xw[src * 256 + c0];
        acc0.x += pp * w.x; acc0.y += pp * w.y;
        acc0.z += pp * w.z; acc0.w += pp * w.w;
    }

    // ---- hop 1 (collapsed weighted entries; self doubled) ----
    ad = g_att[n * 32 + 24 + head];
    t  = g_att[n * 32 + 16 + head] + ad;
    t = (t > 0.f) ? t : 0.2f * t;
    p = 2.0f * __expf(t);
    float sum1 = p;
    v = *(const float4*)&g_xw[n * 256 + 128 + c0];
    float4 acc1 = make_float4(p * v.x, p * v.y, p * v.z, p * v.w);
    je = g_off[N_NODES + n + 1];
    for (int j = g_off[N_NODES + n]; j < je; j++) {
        int ent = g_srcarr[j];
        int src = ent & 0xFFFF;
        float wgt = (float)(ent >> 16);
        float tt = g_att[src * 32 + 16 + head] + ad;
        tt = (tt > 0.f) ? tt : 0.2f * tt;
        float pp = wgt * __expf(tt);
        sum1 += pp;
        float4 w = *(const float4*)&g_xw[src * 256 + 128 + c0];
        acc1.x += pp * w.x; acc1.y += pp * w.y;
        acc1.z += pp * w.z; acc1.w += pp * w.w;
    }

    // ---- bias + residual + LN ----
    float i0 = 1.f / sum0, i1 = 1.f / sum1;
    float4 bb0 = *(const float4*)&b0[c0];
    float4 bb1 = *(const float4*)&b1[c0];
    float4 x0 = *(const float4*)&x[n * 256 + c0];
    float4 x1 = *(const float4*)&x[n * 256 + 128 + c0];
    float vv[8];
    vv[0] = acc0.x * i0 + bb0.x + x0.x;
    vv[1] = acc0.y * i0 + bb0.y + x0.y;
    vv[2] = acc0.z * i0 + bb0.z + x0.z;
    vv[3] = acc0.w * i0 + bb0.w + x0.w;
    vv[4] = acc1.x * i1 + bb1.x + x1.x;
    vv[5] = acc1.y * i1 + bb1.y + x1.y;
    vv[6] = acc1.z * i1 + bb1.z + x1.z;
    vv[7] = acc1.w * i1 + bb1.w + x1.w;

    float s = 0.f, s2 = 0.f;
#pragma unroll
    for (int i = 0; i < 8; i++) { s += vv[i]; s2 += vv[i] * vv[i]; }
#pragma unroll
    for (int off = 16; off > 0; off >>= 1) {
        s  += __shfl_xor_sync(0xffffffffu, s, off);
        s2 += __shfl_xor_sync(0xffffffffu, s2, off);
    }
    float mean = s * (1.f / 256.f);
    float var  = s2 * (1.f / 256.f) - mean * mean;
    float rs   = rsqrtf(var + 1e-5f);

    float4 g0 = *(const float4*)&gamma[c0];
    float4 g1 = *(const float4*)&gamma[128 + c0];
    float4 be0 = *(const float4*)&beta[c0];
    float4 be1 = *(const float4*)&beta[128 + c0];
    float4 o0, o1;
    o0.x = (vv[0] - mean) * rs * g0.x + be0.x;
    o0.y = (vv[1] - mean) * rs * g0.y + be0.y;
    o0.z = (vv[2] - mean) * rs * g0.z + be0.z;
    o0.w = (vv[3] - mean) * rs * g0.w + be0.w;
    o1.x = (vv[4] - mean) * rs * g1.x + be1.x;
    o1.y = (vv[5] - mean) * rs * g1.y + be1.y;
    o1.z = (vv[6] - mean) * rs * g1.z + be1.z;
    o1.w = (vv[7] - mean) * rs * g1.w + be1.w;
    *(float4*)&out[n * 256 + c0]       = o0;
    *(float4*)&out[n * 256 + 128 + c0] = o1;
}

// ---------------- launch (single stream; gemm moved to 4th slot so the
// ncu capture (which lands on launch idx 3) profiles it) ----------------------
extern "C" void kernel_launch(void* const* d_in, const int* in_sizes, int n_in,
                              void* d_out, int out_size) {
    const float* x     = (const float*)d_in[0];
    const int*   ei    = (const int*)d_in[1];
    const float* W0    = (const float*)d_in[2];
    const float* as0   = (const float*)d_in[3];
    const float* ad0   = (const float*)d_in[4];
    const float* b0    = (const float*)d_in[5];
    const float* W1    = (const float*)d_in[6];
    const float* as1   = (const float*)d_in[7];
    const float* ad1   = (const float*)d_in[8];
    const float* b1    = (const float*)d_in[9];
    const float* gamma = (const float*)d_in[10];
    const float* beta  = (const float*)d_in[11];
    float* out = (float*)d_out;

    const int* row = ei;
    const int* col = ei + N_EDGES;

    zero_kernel<<<(TWO_N + 255) / 256, 256>>>();                       // idx 0
    wsplit_kernel<<<256, 256>>>(W0, W1);                               // idx 1
    count0_kernel<<<(N_EDGES + 255) / 256, 256>>>(col);                // idx 2
    gemm_hmma_kernel<<<dim3((N_NODES + 127) / 128, 2), 256>>>(         // idx 3
        x, as0, ad0, as1, ad1);
    count1_kernel<<<(N_NODES + 255) / 256, 256>>>(col);
    scanA_kernel<<<SCAN_NBLK, SCAN_BLK>>>();
    scanB_kernel<<<1, 128>>>();
    scanC_kernel<<<SCAN_NBLK, SCAN_BLK>>>();
    scatter_kernel<<<(N_EDGES + N_NODES + 255) / 256, 256>>>(row, col);
    agg_ln_kernel<<<(N_NODES * 32 + 255) / 256, 256>>>(b0, b1, x, gamma, beta, out);
}